// round 1
// baseline (speedup 1.0000x reference)
#include <cuda_runtime.h>

// PS-ROI-Align, fixed problem dims:
//   input: (N=4, C=490, H=100, W=100) f32
//   rois:  (K=2048, 5) f32  [batch, x1, y1, x2, y2]
//   out:   (K, C_out=10, 7, 7) f32
// POOL_H = POOL_W = 7, SPATIAL_SCALE = 0.0625, GRID = 2
//
// PS property: channel c = co*49 + ph*7 + pw == linear index r within the
// 490-element output slice for a given roi. One thread per output element.

#define C_TOT   490
#define HH      100
#define WW      100
#define POOL    7
#define SSCALE  0.0625f
#define TOTAL   (2048 * 490)

__global__ __launch_bounds__(256) void psroi_align_kernel(
    const float* __restrict__ input,
    const float* __restrict__ rois,
    float* __restrict__ out)
{
    int idx = blockIdx.x * blockDim.x + threadIdx.x;
    if (idx >= TOTAL) return;

    int k = idx / C_TOT;
    int r = idx - k * C_TOT;          // == channel index c
    int pw = r % POOL;
    int ph = (r / POOL) % POOL;

    const float* roi = rois + k * 5;
    int   b  = (int)__ldg(roi + 0);
    float x1 = __ldg(roi + 1) * SSCALE - 0.5f;
    float y1 = __ldg(roi + 2) * SSCALE - 0.5f;
    float x2 = __ldg(roi + 3) * SSCALE - 0.5f;
    float y2 = __ldg(roi + 4) * SSCALE - 0.5f;

    float bsh = (y2 - y1) * (1.0f / POOL);
    float bsw = (x2 - x1) * (1.0f / POOL);

    const float* base = input + ((long)b * C_TOT + r) * (HH * WW);

    float acc = 0.0f;

    #pragma unroll
    for (int gy = 0; gy < 2; ++gy) {
        float y = y1 + ((float)ph + ((float)gy + 0.5f) * 0.5f) * bsh;
        bool vy = (y >= -1.0f) && (y <= (float)HH);
        float ty = fmaxf(y, 0.0f);
        int   yl = min((int)floorf(ty), HH - 1);
        int   yh = min(yl + 1, HH - 1);
        float fy = (yl >= HH - 1) ? 0.0f : (ty - (float)yl);

        #pragma unroll
        for (int gx = 0; gx < 2; ++gx) {
            float x = x1 + ((float)pw + ((float)gx + 0.5f) * 0.5f) * bsw;
            bool vx = (x >= -1.0f) && (x <= (float)WW);
            float tx = fmaxf(x, 0.0f);
            int   xl = min((int)floorf(tx), WW - 1);
            int   xh = min(xl + 1, WW - 1);
            float fx = (xl >= WW - 1) ? 0.0f : (tx - (float)xl);

            if (vy && vx) {
                float v00 = __ldg(base + yl * WW + xl);
                float v01 = __ldg(base + yl * WW + xh);
                float v10 = __ldg(base + yh * WW + xl);
                float v11 = __ldg(base + yh * WW + xh);
                float top = v00 + fx * (v01 - v00);
                float bot = v10 + fx * (v11 - v10);
                acc += top + fy * (bot - top);
            }
        }
    }

    out[idx] = acc * 0.25f;
}

extern "C" void kernel_launch(void* const* d_in, const int* in_sizes, int n_in,
                              void* d_out, int out_size)
{
    const float* input = (const float*)d_in[0];
    const float* rois  = (const float*)d_in[1];
    float* out = (float*)d_out;

    int threads = 256;
    int blocks = (TOTAL + threads - 1) / threads;
    psroi_align_kernel<<<blocks, threads>>>(input, rois, out);
}

// round 2
// speedup vs baseline: 1.1505x; 1.1505x over previous
#include <cuda_runtime.h>

// PS-ROI-Align, fixed dims:
//   input: (N=4, C=490, H=100, W=100) f32
//   rois:  (K=2048, 5) f32  [batch, x1, y1, x2, y2]
//   out:   (K, 10, 7, 7) f32,  POOL=7, SCALE=1/16, GRID=2
//
// One thread per output element (channel c == linear slice index r).
// Optimization: all 4 x-taps of a row fit in one aligned 8-float window
// (2x LDG.128). Per-thread x-weight vector built once; per distinct y-row,
// dot8 against the window. Rows deduped. All taps provably valid
// (x in [-0.5, 99.5]), so no validity masking needed.

#define C_TOT   490
#define HH      100
#define WW      100
#define POOL    7
#define SSCALE  0.0625f
#define TOTAL   (2048 * 490)

__global__ __launch_bounds__(256) void psroi_align_kernel(
    const float* __restrict__ input,
    const float* __restrict__ rois,
    float* __restrict__ out)
{
    int idx = blockIdx.x * blockDim.x + threadIdx.x;
    if (idx >= TOTAL) return;

    int k = idx / C_TOT;
    int r = idx - k * C_TOT;          // == channel index c
    int pw = r % POOL;
    int ph = (r / POOL) % POOL;

    const float* roi = rois + k * 5;
    int   b  = (int)__ldg(roi + 0);
    float x1 = __ldg(roi + 1) * SSCALE - 0.5f;
    float y1 = __ldg(roi + 2) * SSCALE - 0.5f;
    float x2 = __ldg(roi + 3) * SSCALE - 0.5f;
    float y2 = __ldg(roi + 4) * SSCALE - 0.5f;

    float bsh = (y2 - y1) * (1.0f / POOL);
    float bsw = (x2 - x1) * (1.0f / POOL);

    const float* base = input + ((long)b * C_TOT + r) * (HH * WW);

    // ---- x taps (2 samples: gx=0 at +0.25, gx=1 at +0.75 of bin) ----
    float tx0 = fmaxf(x1 + ((float)pw + 0.25f) * bsw, 0.0f);
    float tx1 = fmaxf(x1 + ((float)pw + 0.75f) * bsw, 0.0f);
    int xl0 = min((int)tx0, WW - 1);
    int xl1 = min((int)tx1, WW - 1);
    int xh0 = min(xl0 + 1, WW - 1);
    int xh1 = min(xl1 + 1, WW - 1);
    float fx0 = (xl0 >= WW - 1) ? 0.0f : tx0 - (float)xl0;
    float fx1 = (xl1 >= WW - 1) ? 0.0f : tx1 - (float)xl1;

    // ---- y taps ----
    float ty0 = fmaxf(y1 + ((float)ph + 0.25f) * bsh, 0.0f);
    float ty1 = fmaxf(y1 + ((float)ph + 0.75f) * bsh, 0.0f);
    int yl0 = min((int)ty0, HH - 1);
    int yl1 = min((int)ty1, HH - 1);
    int yh0 = min(yl0 + 1, HH - 1);
    int yh1 = min(yl1 + 1, HH - 1);
    float fy0 = (yl0 >= HH - 1) ? 0.0f : ty0 - (float)yl0;
    float fy1 = (yl1 >= HH - 1) ? 0.0f : ty1 - (float)yl1;

    float a0 = 1.0f - fy0, a1 = fy0;
    float a2 = 1.0f - fy1, a3 = fy1;

    // aligned 8-float x window
    int wbase = min(xl0 & ~3, WW - 8);
    int o_l0 = xl0 - wbase, o_h0 = xh0 - wbase;
    int o_l1 = xl1 - wbase, o_h1 = xh1 - wbase;

    float acc;

    if (o_h1 <= 7) {
        // x-weight vector over the 8-float window (same for every row)
        float w[8];
        #pragma unroll
        for (int j = 0; j < 8; ++j) {
            float v = (j == o_l0) ? (1.0f - fx0) : 0.0f;
            v += (j == o_h0) ? fx0 : 0.0f;
            v += (j == o_l1) ? (1.0f - fx1) : 0.0f;
            v += (j == o_h1) ? fx1 : 0.0f;
            w[j] = v;
        }

        const float* rowbase = base + wbase;
        auto dotrow = [&](int y) -> float {
            const float4* p = (const float4*)(rowbase + y * WW);
            float4 f0 = __ldg(p);
            float4 f1 = __ldg(p + 1);
            return f0.x * w[0] + f0.y * w[1] + f0.z * w[2] + f0.w * w[3]
                 + f1.x * w[4] + f1.y * w[5] + f1.z * w[6] + f1.w * w[7];
        };

        if (yl1 == yl0) {
            // both gy samples share the same row pair
            acc = (a0 + a2) * dotrow(yl0) + (a1 + a3) * dotrow(yh0);
        } else if (yl1 == yh0) {
            acc = a0 * dotrow(yl0) + (a1 + a2) * dotrow(yh0) + a3 * dotrow(yh1);
        } else {
            acc = a0 * dotrow(yl0) + a1 * dotrow(yh0)
                + a2 * dotrow(yl1) + a3 * dotrow(yh1);
        }
    } else {
        // rare wide-roi fallback: scalar taps
        float wx0 = 1.0f - fx0, wx1 = fx0, wx2 = 1.0f - fx1, wx3 = fx1;
        const float* r0 = base + yl0 * WW;
        const float* r1 = base + yh0 * WW;
        const float* r2 = base + yl1 * WW;
        const float* r3 = base + yh1 * WW;
        float s0 = wx0 * __ldg(r0 + xl0) + wx1 * __ldg(r0 + xh0)
                 + wx2 * __ldg(r0 + xl1) + wx3 * __ldg(r0 + xh1);
        float s1 = wx0 * __ldg(r1 + xl0) + wx1 * __ldg(r1 + xh0)
                 + wx2 * __ldg(r1 + xl1) + wx3 * __ldg(r1 + xh1);
        float s2 = wx0 * __ldg(r2 + xl0) + wx1 * __ldg(r2 + xh0)
                 + wx2 * __ldg(r2 + xl1) + wx3 * __ldg(r2 + xh1);
        float s3 = wx0 * __ldg(r3 + xl0) + wx1 * __ldg(r3 + xh0)
                 + wx2 * __ldg(r3 + xl1) + wx3 * __ldg(r3 + xh1);
        acc = a0 * s0 + a1 * s1 + a2 * s2 + a3 * s3;
    }

    out[idx] = acc * 0.25f;
}

extern "C" void kernel_launch(void* const* d_in, const int* in_sizes, int n_in,
                              void* d_out, int out_size)
{
    const float* input = (const float*)d_in[0];
    const float* rois  = (const float*)d_in[1];
    float* out = (float*)d_out;

    int threads = 256;
    int blocks = (TOTAL + threads - 1) / threads;
    psroi_align_kernel<<<blocks, threads>>>(input, rois, out);
}

// round 3
// speedup vs baseline: 1.3423x; 1.1667x over previous
#include <cuda_runtime.h>

// PS-ROI-Align, fixed dims:
//   input: (N=4, C=490, H=100, W=100) f32
//   rois:  (K=2048, 5) f32  [batch, x1, y1, x2, y2]
//   out:   (K, 10, 7, 7) f32,  POOL=7, SCALE=1/16, GRID=2
//
// One thread per output element (channel c == linear slice index r).
// Per-row: 1 float4 load always + 1 predicated float4 (window rarely spans
// >4 floats). Row dedup is branch-free: rows 0,1 always, rows 2,3 predicated.
// 2 blocks per roi -> no integer division, warp-uniform roi.

#define C_TOT   490
#define HH      100
#define WW      100
#define POOL    7
#define SSCALE  0.0625f

__global__ __launch_bounds__(256) void psroi_align_kernel(
    const float* __restrict__ input,
    const float* __restrict__ rois,
    float* __restrict__ out)
{
    int k = blockIdx.x >> 1;
    int r = ((blockIdx.x & 1) << 8) + threadIdx.x;   // 0..511
    if (r >= C_TOT) return;

    int pw = r % POOL;
    int ph = (r / POOL) % POOL;

    const float* roi = rois + k * 5;
    int   b  = (int)__ldg(roi + 0);
    float x1 = __ldg(roi + 1) * SSCALE - 0.5f;
    float y1 = __ldg(roi + 2) * SSCALE - 0.5f;
    float x2 = __ldg(roi + 3) * SSCALE - 0.5f;
    float y2 = __ldg(roi + 4) * SSCALE - 0.5f;

    float bsh = (y2 - y1) * (1.0f / POOL);
    float bsw = (x2 - x1) * (1.0f / POOL);

    const float* base = input + ((long)b * C_TOT + r) * (HH * WW);

    // ---- x taps (samples at +0.25, +0.75 of bin) ----
    float tx0 = fmaxf(x1 + ((float)pw + 0.25f) * bsw, 0.0f);
    float tx1 = fmaxf(x1 + ((float)pw + 0.75f) * bsw, 0.0f);
    int xl0 = min((int)tx0, WW - 1);
    int xl1 = min((int)tx1, WW - 1);
    int xh0 = min(xl0 + 1, WW - 1);
    int xh1 = min(xl1 + 1, WW - 1);
    float fx0 = (xl0 >= WW - 1) ? 0.0f : tx0 - (float)xl0;
    float fx1 = (xl1 >= WW - 1) ? 0.0f : tx1 - (float)xl1;

    // ---- y taps ----
    float ty0 = fmaxf(y1 + ((float)ph + 0.25f) * bsh, 0.0f);
    float ty1 = fmaxf(y1 + ((float)ph + 0.75f) * bsh, 0.0f);
    int yl0 = min((int)ty0, HH - 1);
    int yl1 = min((int)ty1, HH - 1);
    int yh0 = min(yl0 + 1, HH - 1);
    int yh1 = min(yl1 + 1, HH - 1);
    float fy0 = (yl0 >= HH - 1) ? 0.0f : ty0 - (float)yl0;
    float fy1 = (yl1 >= HH - 1) ? 0.0f : ty1 - (float)yl1;

    float a0 = 1.0f - fy0, a1 = fy0;
    float a2 = 1.0f - fy1, a3 = fy1;

    // ---- branch-free row dedup ----
    bool same_pair = (yl1 == yl0);            // rows {2,3} duplicate {0,1}
    bool shift_one = (yl1 == yh0);            // row2 == row1
    bool act2 = !same_pair;
    bool act3 = !same_pair && !shift_one;
    int  row2 = shift_one ? yh1 : yl1;
    float w0 = a0 + (same_pair ? a2 : 0.0f);
    float w1 = a1 + (same_pair ? a3 : (shift_one ? a2 : 0.0f));
    float w2 = shift_one ? a3 : a2;
    float w3 = a3;

    // ---- aligned x window, 1 + (predicated) 1 float4 per row ----
    int wbase = xl0 & ~3;                     // <= 96, f0 always in-bounds
    int o_l0 = xl0 - wbase, o_h0 = xh0 - wbase;
    int o_l1 = xl1 - wbase, o_h1 = xh1 - wbase;

    float acc;

    if (o_h1 <= 7) {                          // o_h1 == 8 is the rare fallback
        float w[8];
        #pragma unroll
        for (int j = 0; j < 8; ++j) {
            float v = (j == o_l0) ? (1.0f - fx0) : 0.0f;
            v += (j == o_h0) ? fx0 : 0.0f;
            v += (j == o_l1) ? (1.0f - fx1) : 0.0f;
            v += (j == o_h1) ? fx1 : 0.0f;
            w[j] = v;
        }
        bool need2 = (o_h1 > 3);              // 2nd float4 needed at all
        const float* rowbase = base + wbase;

        auto dotrow = [&](int y) -> float {
            const float4* p = (const float4*)(rowbase + y * WW);
            float4 f0 = __ldg(p);
            float s = f0.x * w[0] + f0.y * w[1] + f0.z * w[2] + f0.w * w[3];
            if (need2) {
                float4 f1 = __ldg(p + 1);
                s += f1.x * w[4] + f1.y * w[5] + f1.z * w[6] + f1.w * w[7];
            }
            return s;
        };

        float s0 = dotrow(yl0);
        float s1 = dotrow(yh0);
        float s2 = act2 ? dotrow(row2) : 0.0f;
        float s3 = act3 ? dotrow(yh1) : 0.0f;
        acc = w0 * s0 + w1 * s1 + w2 * s2 + w3 * s3;
    } else {
        // rare wide-roi fallback: scalar taps
        float wx0 = 1.0f - fx0, wx1 = fx0, wx2 = 1.0f - fx1, wx3 = fx1;
        auto srow = [&](int y) -> float {
            const float* p = base + y * WW;
            return wx0 * __ldg(p + xl0) + wx1 * __ldg(p + xh0)
                 + wx2 * __ldg(p + xl1) + wx3 * __ldg(p + xh1);
        };
        float s0 = srow(yl0);
        float s1 = srow(yh0);
        float s2 = act2 ? srow(row2) : 0.0f;
        float s3 = act3 ? srow(yh1) : 0.0f;
        acc = w0 * s0 + w1 * s1 + w2 * s2 + w3 * s3;
    }

    out[k * C_TOT + r] = acc * 0.25f;
}

extern "C" void kernel_launch(void* const* d_in, const int* in_sizes, int n_in,
                              void* d_out, int out_size)
{
    const float* input = (const float*)d_in[0];
    const float* rois  = (const float*)d_in[1];
    float* out = (float*)d_out;

    psroi_align_kernel<<<2048 * 2, 256>>>(input, rois, out);
}